// round 16
// baseline (speedup 1.0000x reference)
#include <cuda_runtime.h>
#include <cuda_bf16.h>
#include <cstdint>

// Problem constants
#define H   1024
#define B   64
#define S   512
#define W3H 3072            // W row stride (3*H)
#define NPROD 64            // dedicated u2 producer blocks (scheduled first)
#define NSTREAM 512         // streaming blocks
#define BLKS_PER_B 8        // streaming blocks per batch entry
#define ROWS_PER_BLK 64
#define CHUNK_ROWS 4        // rows per TMA chunk
#define NCHUNK (ROWS_PER_BLK / CHUNK_ROWS)       // 16
#define CHUNK_BYTES (CHUNK_ROWS * H * 4)         // 16384

// Scratch (zero-initialized at module load; every launch self-cleans, so each
// graph replay is deterministic).
__device__ float g_u2[H];
__device__ float g_scores[B * S];
__device__ int   g_cnt[B];
__device__ int   g_gcnt;
__device__ int   g_ready;

// ---------------------------------------------------------------------------
// mbarrier / bulk-copy PTX helpers
// ---------------------------------------------------------------------------
__device__ __forceinline__ uint32_t smem_u32(const void* p) {
    return (uint32_t)__cvta_generic_to_shared(p);
}
__device__ __forceinline__ void mbar_init(uint32_t a, uint32_t cnt) {
    asm volatile("mbarrier.init.shared.b64 [%0], %1;" :: "r"(a), "r"(cnt) : "memory");
}
__device__ __forceinline__ void mbar_expect(uint32_t a, uint32_t bytes) {
    asm volatile("mbarrier.arrive.expect_tx.shared.b64 _, [%0], %1;"
                 :: "r"(a), "r"(bytes) : "memory");
}
__device__ __forceinline__ void bulk_g2s(uint32_t dst, const void* src,
                                         uint32_t bytes, uint32_t mbar) {
    asm volatile("cp.async.bulk.shared::cta.global.mbarrier::complete_tx::bytes "
                 "[%0], [%1], %2, [%3];"
                 :: "r"(dst), "l"(src), "r"(bytes), "r"(mbar) : "memory");
}
__device__ __forceinline__ void mbar_wait(uint32_t a, uint32_t parity) {
    uint32_t done;
    do {
        asm volatile("{\n\t.reg .pred p;\n\t"
                     "mbarrier.try_wait.parity.shared.b64 p, [%1], %2, 0x989680;\n\t"
                     "selp.b32 %0, 1, 0, p;\n\t}"
                     : "=r"(done) : "r"(a), "r"(parity) : "memory");
    } while (!done);
}
__device__ __forceinline__ void fence_async_smem() {
    asm volatile("fence.proxy.async.shared::cta;" ::: "memory");
}

// ---------------------------------------------------------------------------
// Megakernel, block-specialized:
//   blocks 0..63    : u2 producers (16 h-rows each, 256 threads = 256 float4
//                     k-columns, MLP=16) -> atomicAdd -> g_ready++
//   blocks 64..575  : streamers — EXACT R12 body. TMA prologue first (no u2
//                     dependency), tid0 spins for g_ready==64 (hidden under
//                     first-chunk flight), stage u2, stream, ticket, softmax.
// 576 blocks, 44 regs / 38KB smem -> ~5 blocks/SM -> single wave; producers
// are wave-1 by schedule order, so the spin cannot deadlock.
// ---------------------------------------------------------------------------
__global__ void __launch_bounds__(256)
k_mega(const float* __restrict__ enc,
       const float* __restrict__ W,
       const float* __restrict__ v,
       float*       __restrict__ out) {
    __shared__ alignas(128) float s_buf[2][CHUNK_ROWS][H];   // 32 KB
    __shared__ alignas(16)  float s_u2[H];                    // 4 KB
    __shared__ float s_part[CHUNK_ROWS][2];
    __shared__ alignas(8) unsigned long long s_mbar[2];
    __shared__ int s_ticket;
    __shared__ float s_sm[256];

    const int tid = threadIdx.x;
    const int bid = blockIdx.x;

    // ================= producers =================
    if (bid < NPROD) {
        const int h0 = bid * 16;
        float4 acc = make_float4(0.f, 0.f, 0.f, 0.f);
#pragma unroll
        for (int j = 0; j < 16; j++) {
            const float vh = __ldg(&v[h0 + j]);
            const float4 w = __ldg((const float4*)(W + (size_t)(h0 + j) * W3H + 2 * H) + tid);
            acc.x += vh * w.x; acc.y += vh * w.y;
            acc.z += vh * w.z; acc.w += vh * w.w;
        }
        float* dst = g_u2 + tid * 4;
        atomicAdd(dst + 0, acc.x);
        atomicAdd(dst + 1, acc.y);
        atomicAdd(dst + 2, acc.z);
        atomicAdd(dst + 3, acc.w);
        __threadfence();                 // release u2 adds before flag
        __syncthreads();
        if (tid == 0) atomicAdd(&g_ready, 1);
        return;
    }

    // ================= streamers =================
    const int sbid = bid - NPROD;        // 0..511
    const int warp = tid >> 5;
    const int lane = tid & 31;
    const int b    = sbid >> 3;
    const int row0 = sbid * ROWS_PER_BLK;

    const uint32_t mb0 = smem_u32(&s_mbar[0]);
    const uint32_t mb1 = smem_u32(&s_mbar[1]);
    const uint32_t sb0 = smem_u32(&s_buf[0][0][0]);
    const uint32_t sb1 = smem_u32(&s_buf[1][0][0]);

    // prologue: both TMA chunks in flight before anything else
    if (tid == 0) {
        mbar_init(mb0, 1);
        mbar_init(mb1, 1);
        fence_async_smem();
        mbar_expect(mb0, CHUNK_BYTES);
        bulk_g2s(sb0, enc + (size_t)row0 * H, CHUNK_BYTES, mb0);
        mbar_expect(mb1, CHUNK_BYTES);
        bulk_g2s(sb1, enc + (size_t)(row0 + CHUNK_ROWS) * H, CHUNK_BYTES, mb1);
        // wait for u2 (hidden under first-chunk TMA flight)
        while (*(volatile int*)&g_ready < NPROD) __nanosleep(32);
        __threadfence();                 // acquire
    }
    __syncthreads();
    ((float4*)s_u2)[tid] = __ldcg(((const float4*)g_u2) + tid);
    __syncthreads();

    const int r    = warp >> 1;          // row within chunk (0..3)
    const int half = warp & 1;           // which half of the row
    const int base = half * 512 + lane * 4;

    for (int c = 0; c < NCHUNK; c++) {
        const uint32_t mb = (c & 1) ? mb1 : mb0;
        mbar_wait(mb, (c >> 1) & 1);

        const float* rowp = &s_buf[c & 1][r][0];
        float acc = 0.f;
#pragma unroll
        for (int k = 0; k < 4; k++) {
            const float4 e = *(const float4*)(rowp + base + k * 128);
            const float4 w = *(const float4*)(s_u2 + base + k * 128);
            acc += e.x * w.x + e.y * w.y + e.z * w.z + e.w * w.w;
        }
#pragma unroll
        for (int off = 16; off > 0; off >>= 1)
            acc += __shfl_xor_sync(0xffffffffu, acc, off);
        if (lane == 0) s_part[r][half] = acc;
        __syncthreads();                 // buffer reads + partials done

        if (tid < CHUNK_ROWS)
            g_scores[row0 + c * CHUNK_ROWS + tid] = s_part[tid][0] + s_part[tid][1];

        if (tid == 0 && c + 2 < NCHUNK) {
            fence_async_smem();
            mbar_expect(mb, CHUNK_BYTES);
            bulk_g2s((c & 1) ? sb1 : sb0,
                     enc + (size_t)(row0 + (c + 2) * CHUNK_ROWS) * H,
                     CHUNK_BYTES, mb);
        }
    }

    // --- single-thread release + ticket ---
    __syncthreads();
    if (tid == 0) {
        __threadfence();
        s_ticket = atomicAdd(&g_cnt[b], 1);
        if (s_ticket == BLKS_PER_B - 1)
            __threadfence();             // acquire for re-reads
    }
    __syncthreads();

    if (s_ticket == BLKS_PER_B - 1) {
        const float* sc = g_scores + b * S;
        const float v0 = __ldcg(&sc[tid]);
        const float v1 = __ldcg(&sc[tid + 256]);

        s_sm[tid] = fmaxf(v0, v1);
        __syncthreads();
#pragma unroll
        for (int st = 128; st > 0; st >>= 1) {
            if (tid < st) s_sm[tid] = fmaxf(s_sm[tid], s_sm[tid + st]);
            __syncthreads();
        }
        const float mx = s_sm[0];
        __syncthreads();

        const float e0 = __expf(v0 - mx);
        const float e1 = __expf(v1 - mx);
        s_sm[tid] = e0 + e1;
        __syncthreads();
#pragma unroll
        for (int st = 128; st > 0; st >>= 1) {
            if (tid < st) s_sm[tid] += s_sm[tid + st];
            __syncthreads();
        }
        const float inv = 1.f / s_sm[0];

        out[b * S + tid]       = e0 * inv;
        out[b * S + tid + 256] = e1 * inv;

        // --- self-clean for the next launch ---
        if (tid == 0) {
            g_cnt[b] = 0;
            __threadfence();
            const int g = atomicAdd(&g_gcnt, 1);
            s_ticket = (g == B - 1) ? 1 : 0;
        }
        __syncthreads();
        if (s_ticket == 1) {
            // globally last softmax: all streamers have consumed u2
            ((float4*)g_u2)[tid] = make_float4(0.f, 0.f, 0.f, 0.f);
            if (tid == 0) { g_gcnt = 0; g_ready = 0; }
        }
    }
}

// ---------------------------------------------------------------------------
// Inputs (metadata order): hidden[2,B,H], encoder_outputs[B,S,H],
//                          W[H,3H], b[H], v[H]
// hidden and b are mathematically irrelevant post-softmax (per-row constants).
// ---------------------------------------------------------------------------
extern "C" void kernel_launch(void* const* d_in, const int* in_sizes, int n_in,
                              void* d_out, int out_size) {
    const float* enc = (const float*)d_in[1];
    const float* W   = (const float*)d_in[2];
    const float* v   = (const float*)d_in[4];
    float* out = (float*)d_out;

    k_mega<<<NPROD + NSTREAM, 256>>>(enc, W, v, out);
}

// round 17
// speedup vs baseline: 1.0072x; 1.0072x over previous
#include <cuda_runtime.h>
#include <cuda_bf16.h>
#include <cstdint>

// Problem constants
#define H   1024
#define B   64
#define S   512
#define W3H 3072            // W row stride (3*H)
#define BLKS_PER_B 8        // 8 blocks per batch entry
#define ROWS_PER_BLK 64     // rows per block
#define CHUNK_ROWS 4        // rows per TMA chunk
#define NCHUNK (ROWS_PER_BLK / CHUNK_ROWS)       // 16
#define CHUNK_BYTES (CHUNK_ROWS * H * 4)         // 16384

// Scratch (zero-initialized at module load; every launch self-cleans, so each
// graph replay is deterministic).
__device__ float g_u2p[4][H];        // 4-way split u2 partials (contention /4)
__device__ float g_scores[B * S];
__device__ int   g_cnt[B];
__device__ int   g_gcnt;

// ---------------------------------------------------------------------------
// mbarrier / bulk-copy PTX helpers
// ---------------------------------------------------------------------------
__device__ __forceinline__ uint32_t smem_u32(const void* p) {
    return (uint32_t)__cvta_generic_to_shared(p);
}
__device__ __forceinline__ void mbar_init(uint32_t a, uint32_t cnt) {
    asm volatile("mbarrier.init.shared.b64 [%0], %1;" :: "r"(a), "r"(cnt) : "memory");
}
__device__ __forceinline__ void mbar_expect(uint32_t a, uint32_t bytes) {
    asm volatile("mbarrier.arrive.expect_tx.shared.b64 _, [%0], %1;"
                 :: "r"(a), "r"(bytes) : "memory");
}
__device__ __forceinline__ void bulk_g2s(uint32_t dst, const void* src,
                                         uint32_t bytes, uint32_t mbar) {
    asm volatile("cp.async.bulk.shared::cta.global.mbarrier::complete_tx::bytes "
                 "[%0], [%1], %2, [%3];"
                 :: "r"(dst), "l"(src), "r"(bytes), "r"(mbar) : "memory");
}
__device__ __forceinline__ void bulk_prefetch_l2(const void* src, uint32_t bytes) {
    asm volatile("cp.async.bulk.prefetch.L2.global [%0], %1;"
                 :: "l"(src), "r"(bytes) : "memory");
}
__device__ __forceinline__ void mbar_wait(uint32_t a, uint32_t parity) {
    uint32_t done;
    do {
        asm volatile("{\n\t.reg .pred p;\n\t"
                     "mbarrier.try_wait.parity.shared.b64 p, [%1], %2, 0x989680;\n\t"
                     "selp.b32 %0, 1, 0, p;\n\t}"
                     : "=r"(done) : "r"(a), "r"(parity) : "memory");
    } while (!done);
}
__device__ __forceinline__ void fence_async_smem() {
    asm volatile("fence.proxy.async.shared::cta;" ::: "memory");
}

// ---------------------------------------------------------------------------
// Kernel 1: u2 partials. grid = (4, 256): 1024 blocks, 1 float4/thread,
// massive TLP (latency-bound read of the 4MB W slice in one shot).
// Partials go to g_u2p[by & 3] -> per-address atomic conflict stays at 64.
// ---------------------------------------------------------------------------
__global__ void k_u2(const float* __restrict__ W, const float* __restrict__ v) {
    const int tx = threadIdx.x & 63;          // k-float4 lane
    const int ty = threadIdx.x >> 6;          // 0..3 -> one h row each
    const int k4 = blockIdx.x * 64 + tx;
    const int h  = blockIdx.y * 4 + ty;

    const float vh = __ldg(&v[h]);
    const float4 w = __ldg((const float4*)(W + (size_t)h * W3H + 2 * H) + k4);
    float4 acc = make_float4(vh * w.x, vh * w.y, vh * w.z, vh * w.w);

    __shared__ float4 sm[4][64];
    sm[ty][tx] = acc;
    __syncthreads();
    if (ty == 0) {
        float4 s = sm[0][tx];
#pragma unroll
        for (int j = 1; j < 4; j++) {
            const float4 p = sm[j][tx];
            s.x += p.x; s.y += p.y; s.z += p.z; s.w += p.w;
        }
        float* dst = g_u2p[blockIdx.y & 3] + k4 * 4;
        atomicAdd(dst + 0, s.x);
        atomicAdd(dst + 1, s.y);
        atomicAdd(dst + 2, s.z);
        atomicAdd(dst + 3, s.w);
    }
}

// ---------------------------------------------------------------------------
// Kernel 2: EXACT R12 streaming structure + L2 bulk-prefetch lookahead.
// TMA fetches chunk c+2 (smem pipeline) while cp.async.bulk.prefetch.L2
// pulls chunk c+4 DRAM->L2, doubling memory lookahead at zero smem cost.
// u2 staged in smem as sum of the 4 partial buffers.
// ---------------------------------------------------------------------------
__global__ void __launch_bounds__(256)
k_fused(const float* __restrict__ enc, float* __restrict__ out) {
    __shared__ alignas(128) float s_buf[2][CHUNK_ROWS][H];   // 32 KB
    __shared__ alignas(16)  float s_u2[H];                    // 4 KB
    __shared__ float s_part[CHUNK_ROWS][2];
    __shared__ alignas(8) unsigned long long s_mbar[2];
    __shared__ int s_ticket;
    __shared__ float s_sm[256];

    const int tid  = threadIdx.x;
    const int warp = tid >> 5;
    const int lane = tid & 31;
    const int b    = blockIdx.x >> 3;
    const int row0 = blockIdx.x * ROWS_PER_BLK;

    // stage u2 = sum of 4 partial buffers (fresh via L2)
    {
        float4 s = __ldcg(((const float4*)g_u2p[0]) + tid);
#pragma unroll
        for (int j = 1; j < 4; j++) {
            const float4 p = __ldcg(((const float4*)g_u2p[j]) + tid);
            s.x += p.x; s.y += p.y; s.z += p.z; s.w += p.w;
        }
        ((float4*)s_u2)[tid] = s;
    }

    const uint32_t mb0 = smem_u32(&s_mbar[0]);
    const uint32_t mb1 = smem_u32(&s_mbar[1]);
    const uint32_t sb0 = smem_u32(&s_buf[0][0][0]);
    const uint32_t sb1 = smem_u32(&s_buf[1][0][0]);

    if (tid == 0) {
        mbar_init(mb0, 1);
        mbar_init(mb1, 1);
        fence_async_smem();
        mbar_expect(mb0, CHUNK_BYTES);
        bulk_g2s(sb0, enc + (size_t)row0 * H, CHUNK_BYTES, mb0);
        mbar_expect(mb1, CHUNK_BYTES);
        bulk_g2s(sb1, enc + (size_t)(row0 + CHUNK_ROWS) * H, CHUNK_BYTES, mb1);
        // L2 lookahead for chunks 2 and 3
        bulk_prefetch_l2(enc + (size_t)(row0 + 2 * CHUNK_ROWS) * H, CHUNK_BYTES);
        bulk_prefetch_l2(enc + (size_t)(row0 + 3 * CHUNK_ROWS) * H, CHUNK_BYTES);
    }
    __syncthreads();

    const int r    = warp >> 1;        // row within chunk (0..3)
    const int half = warp & 1;         // which half of the row
    const int base = half * 512 + lane * 4;   // float index into row

    for (int c = 0; c < NCHUNK; c++) {
        const uint32_t mb = (c & 1) ? mb1 : mb0;
        mbar_wait(mb, (c >> 1) & 1);

        const float* rowp = &s_buf[c & 1][r][0];
        float acc = 0.f;
#pragma unroll
        for (int k = 0; k < 4; k++) {
            const float4 e = *(const float4*)(rowp + base + k * 128);
            const float4 w = *(const float4*)(s_u2 + base + k * 128);
            acc += e.x * w.x + e.y * w.y + e.z * w.z + e.w * w.w;
        }
#pragma unroll
        for (int off = 16; off > 0; off >>= 1)
            acc += __shfl_xor_sync(0xffffffffu, acc, off);
        if (lane == 0) s_part[r][half] = acc;
        __syncthreads();                      // buffer reads + partials done

        if (tid < CHUNK_ROWS)
            g_scores[row0 + c * CHUNK_ROWS + tid] = s_part[tid][0] + s_part[tid][1];

        if (tid == 0 && c + 2 < NCHUNK) {
            fence_async_smem();               // order smem reads before async reuse
            mbar_expect(mb, CHUNK_BYTES);
            bulk_g2s((c & 1) ? sb1 : sb0,
                     enc + (size_t)(row0 + (c + 2) * CHUNK_ROWS) * H,
                     CHUNK_BYTES, mb);
            if (c + 4 < NCHUNK)               // L2 lookahead two chunks further
                bulk_prefetch_l2(enc + (size_t)(row0 + (c + 4) * CHUNK_ROWS) * H,
                                 CHUNK_BYTES);
        }
    }

    // --- single-thread release + ticket ---
    __syncthreads();
    if (tid == 0) {
        __threadfence();
        s_ticket = atomicAdd(&g_cnt[b], 1);
        if (s_ticket == BLKS_PER_B - 1)
            __threadfence();                  // acquire for re-reads
    }
    __syncthreads();

    if (s_ticket == BLKS_PER_B - 1) {
        const float* sc = g_scores + b * S;
        const float v0 = __ldcg(&sc[tid]);
        const float v1 = __ldcg(&sc[tid + 256]);

        s_sm[tid] = fmaxf(v0, v1);
        __syncthreads();
#pragma unroll
        for (int st = 128; st > 0; st >>= 1) {
            if (tid < st) s_sm[tid] = fmaxf(s_sm[tid], s_sm[tid + st]);
            __syncthreads();
        }
        const float mx = s_sm[0];
        __syncthreads();

        const float e0 = __expf(v0 - mx);
        const float e1 = __expf(v1 - mx);
        s_sm[tid] = e0 + e1;
        __syncthreads();
#pragma unroll
        for (int st = 128; st > 0; st >>= 1) {
            if (tid < st) s_sm[tid] += s_sm[tid + st];
            __syncthreads();
        }
        const float inv = 1.f / s_sm[0];

        out[b * S + tid]       = e0 * inv;
        out[b * S + tid + 256] = e1 * inv;

        // --- self-clean for the next launch ---
        if (tid == 0) {
            g_cnt[b] = 0;
            __threadfence();
            const int g = atomicAdd(&g_gcnt, 1);
            s_ticket = (g == B - 1) ? 1 : 0;
        }
        __syncthreads();
        if (s_ticket == 1) {
            // zero all 4 partial buffers (4 x 1024 floats = 4 float4/thread)
#pragma unroll
            for (int j = 0; j < 4; j++)
                ((float4*)g_u2p[j])[tid] = make_float4(0.f, 0.f, 0.f, 0.f);
            if (tid == 0) g_gcnt = 0;
        }
    }
}

// ---------------------------------------------------------------------------
// Inputs (metadata order): hidden[2,B,H], encoder_outputs[B,S,H],
//                          W[H,3H], b[H], v[H]
// hidden and b are mathematically irrelevant post-softmax (per-row constants).
// ---------------------------------------------------------------------------
extern "C" void kernel_launch(void* const* d_in, const int* in_sizes, int n_in,
                              void* d_out, int out_size) {
    const float* enc = (const float*)d_in[1];
    const float* W   = (const float*)d_in[2];
    const float* v   = (const float*)d_in[4];
    float* out = (float*)d_out;

    {
        dim3 grid(4, 256);
        k_u2<<<grid, 256>>>(W, v);
    }
    k_fused<<<B * BLKS_PER_B, 256>>>(enc, out);
}